// round 3
// baseline (speedup 1.0000x reference)
#include <cuda_runtime.h>
#include <cuda_bf16.h>
#include <cstdint>
#include <math_constants.h>

// Problem constants
#define NT 8192      // tokens = 8*32*32
#define KC 8192      // codebook size
#define DD 256       // embedding dim
#define BHW 1024     // 32*32
#define NELEM 2097152  // 8*256*32*32

// Output layout (float32, concatenated in reference return order)
#define OFF_ZQ   0
#define OFF_LOSS 2097152
#define OFF_IDX  2097153
#define OFF_CS   2105345
#define OFF_EMAW 2113537
#define OFF_EMB  4210689

// ---------------- device scratch (no cudaMalloc allowed) ----------------
static __device__ __nv_bfloat16 g_zbf[(size_t)NT * DD];    // 4 MB  [t][d]
static __device__ __nv_bfloat16 g_ebf[(size_t)KC * DD];    // 4 MB  [k][d]
static __device__ float         g_enorm[KC];
static __device__ __nv_bfloat16 g_acc[(size_t)NT * KC];    // 128 MB dump of z.e (bf16)
static __device__ int           g_idx[NT];
static __device__ float         g_counts[KC];
static __device__ float         g_dw[(size_t)KC * DD];     // 8 MB
static __device__ float         g_ncsraw[KC];
static __device__ float         g_red[2];                  // [0]=sum(new_cs), [1]=loss sum

// ---------------- K0a: convert embedding to bf16, zero scratch ----------------
__global__ void k_prep(const float* __restrict__ emb) {
    int i = blockIdx.x * 256 + threadIdx.x;
    g_ebf[i] = __float2bfloat16(emb[i]);
    g_dw[i] = 0.0f;
    if (i < KC) g_counts[i] = 0.0f;
    if (i < 2)  g_red[i] = 0.0f;
}

// ---------------- K0b: ||e||^2 per code (one warp per code) ----------------
__global__ void k_enorm(const float* __restrict__ emb) {
    int wid = threadIdx.x >> 5, lane = threadIdx.x & 31;
    int k = blockIdx.x * 8 + wid;
    const float* e = emb + (size_t)k * DD;
    float s = 0.0f;
    #pragma unroll
    for (int d = lane; d < DD; d += 32) { float v = e[d]; s += v * v; }
    #pragma unroll
    for (int o = 16; o > 0; o >>= 1) s += __shfl_down_sync(0xffffffffu, s, o);
    if (lane == 0) g_enorm[k] = s;
}

// ---------------- K0c: transpose z [B,C,H,W] -> zbf [t][d] bf16 ----------------
__global__ void k_transpose(const float* __restrict__ z) {
    __shared__ float tile[32][33];
    int b = blockIdx.z, d0 = blockIdx.y * 32, hw0 = blockIdx.x * 32;
    int x = threadIdx.x, y = threadIdx.y;
    const float* zb = z + (size_t)b * (DD * BHW);
    #pragma unroll
    for (int yy = y; yy < 32; yy += 8)
        tile[yy][x] = zb[(size_t)(d0 + yy) * BHW + hw0 + x];
    __syncthreads();
    #pragma unroll
    for (int yy = y; yy < 32; yy += 8)
        g_zbf[(size_t)(b * BHW + hw0 + yy) * DD + d0 + x] = __float2bfloat16(tile[x][yy]);
}

// ---------------- K1: bf16 GEMM (z.e), dump acc as bf16 ----------------
#define BM 128
#define BN 128
#define BK 64
#define ASTRIDE 88   // 176B row stride: conflict-free for frag loads, 16B aligned

__device__ __forceinline__ void mma16816(float* c, const unsigned* a, const unsigned* b) {
    asm volatile(
        "mma.sync.aligned.m16n8k16.row.col.f32.bf16.bf16.f32 "
        "{%0,%1,%2,%3}, {%4,%5,%6,%7}, {%8,%9}, {%0,%1,%2,%3};\n"
        : "+f"(c[0]), "+f"(c[1]), "+f"(c[2]), "+f"(c[3])
        : "r"(a[0]), "r"(a[1]), "r"(a[2]), "r"(a[3]), "r"(b[0]), "r"(b[1]));
}

__device__ __forceinline__ unsigned pack2(float x, float y) {
    __nv_bfloat162 v = __floats2bfloat162_rn(x, y);
    return *reinterpret_cast<unsigned*>(&v);
}

__global__ __launch_bounds__(256) void k_gemm() {
    __shared__ __nv_bfloat16 As[BM * ASTRIDE];
    __shared__ __nv_bfloat16 Bs[BN * ASTRIDE];
    int t0 = blockIdx.y * BM, k0 = blockIdx.x * BN;
    int tid = threadIdx.x;
    int w = tid >> 5, lane = tid & 31;
    int wm = w >> 2, wn = w & 3;           // 2 x 4 warp grid, 64x32 warp tile
    int g = lane >> 2, tg = lane & 3;

    float acc[4][4][4];
    #pragma unroll
    for (int mi = 0; mi < 4; ++mi)
        #pragma unroll
        for (int ni = 0; ni < 4; ++ni)
            #pragma unroll
            for (int r = 0; r < 4; ++r) acc[mi][ni][r] = 0.0f;

    for (int it = 0; it < 4; ++it) {
        #pragma unroll
        for (int p = 0; p < 4; ++p) {
            int idx = p * 2048 + tid * 8;
            int row = idx >> 6, col = idx & 63;
            *(uint4*)(As + row * ASTRIDE + col) =
                *(const uint4*)(g_zbf + (size_t)(t0 + row) * DD + it * 64 + col);
            *(uint4*)(Bs + row * ASTRIDE + col) =
                *(const uint4*)(g_ebf + (size_t)(k0 + row) * DD + it * 64 + col);
        }
        __syncthreads();
        #pragma unroll
        for (int ks = 0; ks < 4; ++ks) {
            int kb = ks * 16;
            unsigned a[4][4], bfr[4][2];
            #pragma unroll
            for (int mi = 0; mi < 4; ++mi) {
                int r = (wm * 64 + mi * 16 + g) * ASTRIDE;
                a[mi][0] = *(unsigned*)(As + r + kb + tg * 2);
                a[mi][1] = *(unsigned*)(As + r + 8 * ASTRIDE + kb + tg * 2);
                a[mi][2] = *(unsigned*)(As + r + kb + 8 + tg * 2);
                a[mi][3] = *(unsigned*)(As + r + 8 * ASTRIDE + kb + 8 + tg * 2);
            }
            #pragma unroll
            for (int ni = 0; ni < 4; ++ni) {
                int r = (wn * 32 + ni * 8 + g) * ASTRIDE;
                bfr[ni][0] = *(unsigned*)(Bs + r + kb + tg * 2);
                bfr[ni][1] = *(unsigned*)(Bs + r + kb + 8 + tg * 2);
            }
            #pragma unroll
            for (int mi = 0; mi < 4; ++mi)
                #pragma unroll
                for (int ni = 0; ni < 4; ++ni)
                    mma16816(acc[mi][ni], a[mi], bfr[ni]);
        }
        __syncthreads();
    }

    // epilogue: dump acc (z.e) as bf16 pairs
    #pragma unroll
    for (int mi = 0; mi < 4; ++mi) {
        #pragma unroll
        for (int ni = 0; ni < 4; ++ni) {
            int t = t0 + wm * 64 + mi * 16 + g;
            int kk = k0 + wn * 32 + ni * 8 + tg * 2;
            *(unsigned*)(g_acc + (size_t)t * KC + kk)       = pack2(acc[mi][ni][0], acc[mi][ni][1]);
            *(unsigned*)(g_acc + (size_t)(t + 8) * KC + kk) = pack2(acc[mi][ni][2], acc[mi][ni][3]);
        }
    }
}

// ---------------- K2: per-token argmin replicating the reference's fp32
// rounding. Reference computes d = (||z||^2 + ||e||^2) - 2*(z.e) in fp32 where
// ||z||^2 ~ 256 quantizes the score to ulp(||z||^2) buckets (and ||e||^2 < ulp/2
// vanishes). Equivalent: argmax over fp32-bucketed 2*z.e, first index on ties.
// We prune with the bf16 approx dots, then rescore candidates with the literal
// fp32 expression. Argmin is invariant to ulp-level differences in our znorm
// vs the reference's (same-binade grid shift). ----------------
__global__ __launch_bounds__(256) void k_select(const float* __restrict__ z,
                                                const float* __restrict__ emb) {
    int t = blockIdx.x;
    int tid = threadIdx.x;
    __shared__ float zrow[DD];
    __shared__ float smin[256];
    __shared__ int   sidx[256];
    __shared__ float s_zn;
    int b = t >> 10, hw = t & 1023;
    zrow[tid] = z[(size_t)b * (DD * BHW) + (size_t)tid * BHW + hw];
    __syncthreads();

    // znorm (any fp32 summation order is fine — argmin invariant to grid shifts)
    smin[tid] = zrow[tid] * zrow[tid];
    __syncthreads();
    #pragma unroll
    for (int o = 128; o > 0; o >>= 1) {
        if (tid < o) smin[tid] += smin[tid + o];
        __syncthreads();
    }
    if (tid == 0) s_zn = smin[0];
    __syncthreads();
    float zn = s_zn;
    __syncthreads();

    // pass 1: max approximate dot (bf16 MMA result)
    const __nv_bfloat16* arow = g_acc + (size_t)t * KC;
    float lmax = -CUDART_INF_F;
    for (int j = tid; j < KC; j += 256)
        lmax = fmaxf(lmax, __bfloat162float(arow[j]));
    smin[tid] = lmax;
    __syncthreads();
    #pragma unroll
    for (int o = 128; o > 0; o >>= 1) {
        if (tid < o) smin[tid] = fmaxf(smin[tid], smin[tid + o]);
        __syncthreads();
    }
    // margin covers worst-case bf16 MMA error (~6e-5) + bucket width (~3e-5)
    float thr = smin[0] - 4e-4f;
    __syncthreads();

    // pass 2: exact fp32 rescore of candidates, replicating reference rounding
    float bv = CUDART_INF_F; int bi = 0x7fffffff;
    for (int j = tid; j < KC; j += 256) {
        if (__bfloat162float(arow[j]) >= thr) {
            const float* e = emb + (size_t)j * DD;
            float d0 = 0.f, d1 = 0.f, d2 = 0.f, d3 = 0.f;
            #pragma unroll 4
            for (int d = 0; d < DD; d += 4) {
                d0 += zrow[d]     * e[d];
                d1 += zrow[d + 1] * e[d + 1];
                d2 += zrow[d + 2] * e[d + 2];
                d3 += zrow[d + 3] * e[d + 3];
            }
            float dot = (d0 + d1) + (d2 + d3);
            // literal reference expression: (zn + enorm) - 2*dot, fp32 ops
            float s = __fsub_rn(__fadd_rn(zn, g_enorm[j]), __fmul_rn(2.0f, dot));
            if (s < bv || (s == bv && j < bi)) { bv = s; bi = j; }
        }
    }
    smin[tid] = bv; sidx[tid] = bi;
    __syncthreads();
    #pragma unroll
    for (int o = 128; o > 0; o >>= 1) {
        if (tid < o) {
            float ov = smin[tid + o]; int oi = sidx[tid + o];
            if (ov < smin[tid] || (ov == smin[tid] && oi < sidx[tid])) {
                smin[tid] = ov; sidx[tid] = oi;
            }
        }
        __syncthreads();
    }
    int best = sidx[0];
    if (tid == 0) { g_idx[t] = best; atomicAdd(&g_counts[best], 1.0f); }
    atomicAdd(&g_dw[(size_t)best * DD + tid], zrow[tid]);
}

// ---------------- K3: new cluster size raw + global sum ----------------
__global__ void k_ncs(const float* __restrict__ cs) {
    __shared__ float sm[256];
    int k = blockIdx.x * 256 + threadIdx.x;
    float raw = cs[k] * 0.99f + 0.01f * g_counts[k];
    g_ncsraw[k] = raw;
    sm[threadIdx.x] = raw;
    __syncthreads();
    #pragma unroll
    for (int o = 128; o > 0; o >>= 1) {
        if (threadIdx.x < o) sm[threadIdx.x] += sm[threadIdx.x + o];
        __syncthreads();
    }
    if (threadIdx.x == 0) atomicAdd(&g_red[0], sm[0]);
}

// ---------------- K4: ema_w, embedding, new_cs outputs ----------------
__global__ void k_final(const float* __restrict__ emaw, float* __restrict__ out) {
    int i = blockIdx.x * 256 + threadIdx.x;
    int k = i >> 8, d = i & 255;
    float n = g_red[0];
    float ncs = (g_ncsraw[k] + 1e-5f) / (n + 0.08192f) * n;
    float w = emaw[i] * 0.99f + 0.01f * g_dw[i];
    out[OFF_EMAW + i] = w;
    out[OFF_EMB + i] = w / ncs;
    if (d == 0) out[OFF_CS + k] = ncs;
}

// ---------------- K5: z_q gather (NCHW) + loss partial sums ----------------
__global__ void k_zq(const float* __restrict__ z, const float* __restrict__ emb,
                     float* __restrict__ out) {
    __shared__ float sm[256];
    int i = blockIdx.x * 256 + threadIdx.x;   // over NELEM, memory-linear
    int b = i >> 18;
    int rem = i & 262143;
    int d = rem >> 10;
    int hw = rem & 1023;
    int n = (b << 10) | hw;
    float q = emb[(size_t)g_idx[n] * DD + d];
    out[OFF_ZQ + i] = q;
    float df = q - z[i];
    sm[threadIdx.x] = df * df;
    __syncthreads();
    #pragma unroll
    for (int o = 128; o > 0; o >>= 1) {
        if (threadIdx.x < o) sm[threadIdx.x] += sm[threadIdx.x + o];
        __syncthreads();
    }
    if (threadIdx.x == 0) atomicAdd(&g_red[1], sm[0]);
}

// ---------------- K6: loss scalar + idx (as float) ----------------
__global__ void k_tail(float* __restrict__ out) {
    int i = blockIdx.x * 256 + threadIdx.x;
    if (i < NT) out[OFF_IDX + i] = (float)g_idx[i];
    if (i == 0) out[OFF_LOSS] = 1.25f * g_red[1] / 2097152.0f;
}

// ---------------- launch ----------------
extern "C" void kernel_launch(void* const* d_in, const int* in_sizes, int n_in,
                              void* d_out, int out_size) {
    const float* z    = (const float*)d_in[0];
    const float* emb  = (const float*)d_in[1];
    const float* cs   = (const float*)d_in[2];
    const float* emaw = (const float*)d_in[3];
    float* out = (float*)d_out;

    k_prep<<<KC * DD / 256, 256>>>(emb);
    k_enorm<<<KC / 8, 256>>>(emb);
    k_transpose<<<dim3(32, 8, 8), dim3(32, 8)>>>(z);
    k_gemm<<<dim3(KC / BN, NT / BM), 256>>>();
    k_select<<<NT, 256>>>(z, emb);
    k_ncs<<<KC / 256, 256>>>(cs);
    k_final<<<KC * DD / 256, 256>>>(emaw, out);
    k_zq<<<NELEM / 256, 256>>>(z, emb, out);
    k_tail<<<32, 256>>>(out);
}

// round 4
// speedup vs baseline: 1.4715x; 1.4715x over previous
#include <cuda_runtime.h>
#include <cuda_bf16.h>
#include <cstdint>
#include <math_constants.h>

// Problem constants
#define NT 8192      // tokens = 8*32*32
#define KC 8192      // codebook size
#define DD 256       // embedding dim
#define BHW 1024     // 32*32
#define NELEM 2097152  // 8*256*32*32
#define CAP 64       // candidate list capacity per token

// Output layout (float32, concatenated in reference return order)
#define OFF_ZQ   0
#define OFF_LOSS 2097152
#define OFF_IDX  2097153
#define OFF_CS   2105345
#define OFF_EMAW 2113537
#define OFF_EMB  4210689

// ---------------- device scratch (no cudaMalloc allowed) ----------------
static __device__ __nv_bfloat16 g_zbf[(size_t)NT * DD];    // 4 MB  [t][d]
static __device__ __nv_bfloat16 g_ebf[(size_t)KC * DD];    // 4 MB  [k][d]
static __device__ float         g_zf[(size_t)NT * DD];     // 8 MB  [t][d] fp32
static __device__ float         g_enorm[KC];
static __device__ unsigned      g_tokmax[NT];              // ordered-uint running max dot
static __device__ int           g_ccnt[NT];
static __device__ int2          g_cand[(size_t)NT * CAP];  // 4 MB (code, fp32 dot bits)
static __device__ int           g_idx[NT];
static __device__ float         g_counts[KC];
static __device__ float         g_dw[(size_t)KC * DD];     // 8 MB
static __device__ float         g_ncsraw[KC];
static __device__ float         g_red[2];                  // [0]=sum(new_cs), [1]=loss sum

// ordered-uint encoding of float: monotonic for unsigned compare
__device__ __forceinline__ unsigned ford(float f) {
    unsigned b = __float_as_uint(f);
    return (b & 0x80000000u) ? ~b : (b | 0x80000000u);
}
__device__ __forceinline__ float iford(unsigned u) {
    unsigned b = (u & 0x80000000u) ? (u & 0x7fffffffu) : ~u;
    return __uint_as_float(b);
}

// ---------------- K0a: per-code prep: bf16 convert, ||e||^2, zero scratch ----
__global__ __launch_bounds__(256) void k_prep(const float* __restrict__ emb) {
    __shared__ float sm[256];
    int k = blockIdx.x, tid = threadIdx.x;
    float v = emb[(size_t)k * DD + tid];
    g_ebf[(size_t)k * DD + tid] = __float2bfloat16(v);
    g_dw[(size_t)k * DD + tid] = 0.0f;
    sm[tid] = v * v;
    __syncthreads();
    #pragma unroll
    for (int o = 128; o > 0; o >>= 1) {
        if (tid < o) sm[tid] += sm[tid + o];
        __syncthreads();
    }
    if (tid == 0) {
        g_enorm[k] = sm[0];
        g_counts[k] = 0.0f;
        g_tokmax[k] = 0u;     // below ford(-inf)=0x007FFFFF
        g_ccnt[k] = 0;
        if (k < 2) g_red[k] = 0.0f;
    }
}

// ---------------- K0c: transpose z [B,C,H,W] -> [t][d] (bf16 + fp32) --------
__global__ void k_transpose(const float* __restrict__ z) {
    __shared__ float tile[32][33];
    int b = blockIdx.z, d0 = blockIdx.y * 32, hw0 = blockIdx.x * 32;
    int x = threadIdx.x, y = threadIdx.y;
    const float* zb = z + (size_t)b * (DD * BHW);
    #pragma unroll
    for (int yy = y; yy < 32; yy += 8)
        tile[yy][x] = zb[(size_t)(d0 + yy) * BHW + hw0 + x];
    __syncthreads();
    #pragma unroll
    for (int yy = y; yy < 32; yy += 8) {
        float v = tile[x][yy];
        size_t o = (size_t)(b * BHW + hw0 + yy) * DD + d0 + x;
        g_zbf[o] = __float2bfloat16(v);
        g_zf[o] = v;
    }
}

// ---------------- K1: bf16 GEMM (z.e) with fused argmax/candidate epilogue --
#define BM 128
#define BN 128
#define ASTRIDE 88   // 176B row stride: conflict-free, 16B aligned
#define BUFBYTES (2 * BM * ASTRIDE * 2)   // As+Bs per stage = 45056 B
#define SMEM_GEMM (2 * BUFBYTES)          // double buffered = 90112 B

__device__ __forceinline__ void mma16816(float* c, const unsigned* a, const unsigned* b) {
    asm volatile(
        "mma.sync.aligned.m16n8k16.row.col.f32.bf16.bf16.f32 "
        "{%0,%1,%2,%3}, {%4,%5,%6,%7}, {%8,%9}, {%0,%1,%2,%3};\n"
        : "+f"(c[0]), "+f"(c[1]), "+f"(c[2]), "+f"(c[3])
        : "r"(a[0]), "r"(a[1]), "r"(a[2]), "r"(a[3]), "r"(b[0]), "r"(b[1]));
}

__device__ __forceinline__ void cpasync16(void* smem, const void* g) {
    unsigned s = (unsigned)__cvta_generic_to_shared(smem);
    asm volatile("cp.async.cg.shared.global [%0], [%1], 16;\n" :: "r"(s), "l"(g));
}
#define CP_COMMIT() asm volatile("cp.async.commit_group;\n" ::: "memory")
#define CP_WAIT(n)  asm volatile("cp.async.wait_group %0;\n" :: "n"(n) : "memory")

__device__ __forceinline__ void load_tile(char* buf, int it, int t0, int k0, int tid) {
    __nv_bfloat16* As = (__nv_bfloat16*)buf;
    __nv_bfloat16* Bs = (__nv_bfloat16*)(buf + BM * ASTRIDE * 2);
    #pragma unroll
    for (int p = 0; p < 4; ++p) {
        int idx = p * 2048 + tid * 8;
        int row = idx >> 6, col = idx & 63;
        cpasync16(As + row * ASTRIDE + col,
                  g_zbf + (size_t)(t0 + row) * DD + it * 64 + col);
        cpasync16(Bs + row * ASTRIDE + col,
                  g_ebf + (size_t)(k0 + row) * DD + it * 64 + col);
    }
}

__global__ __launch_bounds__(256) void k_gemm() {
    extern __shared__ char dynbuf[];
    int t0 = blockIdx.y * BM, k0 = blockIdx.x * BN;
    int tid = threadIdx.x;
    int w = tid >> 5, lane = tid & 31;
    int wm = w >> 2, wn = w & 3;           // 2 x 4 warp grid, 64x32 warp tile
    int g = lane >> 2, tg = lane & 3;

    float acc[4][4][4];
    #pragma unroll
    for (int mi = 0; mi < 4; ++mi)
        #pragma unroll
        for (int ni = 0; ni < 4; ++ni)
            #pragma unroll
            for (int r = 0; r < 4; ++r) acc[mi][ni][r] = 0.0f;

    load_tile(dynbuf, 0, t0, k0, tid);
    CP_COMMIT();

    for (int it = 0; it < 4; ++it) {
        if (it < 3) {
            load_tile(dynbuf + ((it + 1) & 1) * BUFBYTES, it + 1, t0, k0, tid);
            CP_COMMIT();
            CP_WAIT(1);
        } else {
            CP_WAIT(0);
        }
        __syncthreads();

        char* buf = dynbuf + (it & 1) * BUFBYTES;
        __nv_bfloat16* As = (__nv_bfloat16*)buf;
        __nv_bfloat16* Bs = (__nv_bfloat16*)(buf + BM * ASTRIDE * 2);
        #pragma unroll
        for (int ks = 0; ks < 4; ++ks) {
            int kb = ks * 16;
            unsigned a[4][4], bfr[4][2];
            #pragma unroll
            for (int mi = 0; mi < 4; ++mi) {
                int r = (wm * 64 + mi * 16 + g) * ASTRIDE;
                a[mi][0] = *(unsigned*)(As + r + kb + tg * 2);
                a[mi][1] = *(unsigned*)(As + r + 8 * ASTRIDE + kb + tg * 2);
                a[mi][2] = *(unsigned*)(As + r + kb + 8 + tg * 2);
                a[mi][3] = *(unsigned*)(As + r + 8 * ASTRIDE + kb + 8 + tg * 2);
            }
            #pragma unroll
            for (int ni = 0; ni < 4; ++ni) {
                int r = (wn * 32 + ni * 8 + g) * ASTRIDE;
                bfr[ni][0] = *(unsigned*)(Bs + r + kb + tg * 2);
                bfr[ni][1] = *(unsigned*)(Bs + r + kb + 8 + tg * 2);
            }
            #pragma unroll
            for (int mi = 0; mi < 4; ++mi)
                #pragma unroll
                for (int ni = 0; ni < 4; ++ni)
                    mma16816(acc[mi][ni], a[mi], bfr[ni]);
        }
        __syncthreads();
    }

    // -------- fused epilogue: per-token running max + candidate append ------
    unsigned* srm = (unsigned*)dynbuf;          // [128] ordered-uint row max
    float*    sthr = (float*)(dynbuf + 512);    // [128] per-row threshold
    if (tid < 128) srm[tid] = 0u;
    __syncthreads();

    #pragma unroll
    for (int mi = 0; mi < 4; ++mi) {
        float m1 = -CUDART_INF_F, m2 = -CUDART_INF_F;
        #pragma unroll
        for (int ni = 0; ni < 4; ++ni) {
            m1 = fmaxf(m1, fmaxf(acc[mi][ni][0], acc[mi][ni][1]));
            m2 = fmaxf(m2, fmaxf(acc[mi][ni][2], acc[mi][ni][3]));
        }
        #pragma unroll
        for (int o = 1; o <= 2; o <<= 1) {
            m1 = fmaxf(m1, __shfl_xor_sync(0xffffffffu, m1, o));
            m2 = fmaxf(m2, __shfl_xor_sync(0xffffffffu, m2, o));
        }
        if (tg == 0) {
            int r1 = wm * 64 + mi * 16 + g;
            atomicMax(&srm[r1], ford(m1));
            atomicMax(&srm[r1 + 8], ford(m2));
        }
    }
    __syncthreads();

    if (tid < 128) {
        unsigned mine = srm[tid];
        unsigned old = atomicMax(&g_tokmax[t0 + tid], mine);
        unsigned cur = old > mine ? old : mine;
        sthr[tid] = iford(cur) - 4e-4f;
    }
    __syncthreads();

    #pragma unroll
    for (int mi = 0; mi < 4; ++mi) {
        int r1 = wm * 64 + mi * 16 + g;
        float th1 = sthr[r1], th2 = sthr[r1 + 8];
        #pragma unroll
        for (int ni = 0; ni < 4; ++ni) {
            int c0 = k0 + wn * 32 + ni * 8 + tg * 2;
            #pragma unroll
            for (int h = 0; h < 2; ++h) {
                float v1 = acc[mi][ni][h];
                if (v1 >= th1) {
                    int t = t0 + r1;
                    int pos = atomicAdd(&g_ccnt[t], 1);
                    if (pos < CAP) g_cand[(size_t)t * CAP + pos] =
                        make_int2(c0 + h, __float_as_int(v1));
                }
                float v2 = acc[mi][ni][2 + h];
                if (v2 >= th2) {
                    int t = t0 + r1 + 8;
                    int pos = atomicAdd(&g_ccnt[t], 1);
                    if (pos < CAP) g_cand[(size_t)t * CAP + pos] =
                        make_int2(c0 + h, __float_as_int(v2));
                }
            }
        }
    }
}

// ---------------- K2: exact fp32 rescore of candidates (reference rounding) -
// Reference scores d = (||z||^2 + ||e||^2) - 2*(z.e) in fp32; ||z||^2 ~ 256
// buckets everything to ulp(||z||^2). Argmin is invariant to ulp-level shifts
// of our zn (same-binade grid shift), so we evaluate the literal expression
// and tie-break by lowest index. Candidate lists are supersets of all codes
// within 4e-4 of the max dot; extras can never win.
__global__ __launch_bounds__(256) void k_select(const float* __restrict__ emb) {
    int t = blockIdx.x, tid = threadIdx.x;
    int w = tid >> 5, lane = tid & 31;
    __shared__ float zrow[DD];
    __shared__ float red[256];
    __shared__ int   redi[256];
    __shared__ float s_zn;
    __shared__ int   s_best;

    zrow[tid] = g_zf[(size_t)t * DD + tid];
    __syncthreads();
    red[tid] = zrow[tid] * zrow[tid];
    __syncthreads();
    #pragma unroll
    for (int o = 128; o > 0; o >>= 1) {
        if (tid < o) red[tid] += red[tid + o];
        __syncthreads();
    }
    if (tid == 0) s_zn = red[0];
    __syncthreads();
    float zn = s_zn;
    __syncthreads();

    int cnt = g_ccnt[t];
    float bv = CUDART_INF_F; int bi = 0x7fffffff;

    if (cnt <= CAP) {
        // one warp per candidate, 8 dims per lane
        for (int c = w; c < cnt; c += 8) {
            int2 cd = g_cand[(size_t)t * CAP + c];
            int j = cd.x;
            const float* e = emb + (size_t)j * DD;
            float p = 0.0f;
            #pragma unroll
            for (int q = 0; q < 8; ++q)
                p += zrow[lane * 8 + q] * e[lane * 8 + q];
            #pragma unroll
            for (int o = 16; o > 0; o >>= 1)
                p += __shfl_down_sync(0xffffffffu, p, o);
            if (lane == 0) {
                float s = __fsub_rn(__fadd_rn(zn, g_enorm[j]), __fmul_rn(2.0f, p));
                if (s < bv || (s == bv && j < bi)) { bv = s; bi = j; }
            }
        }
    } else {
        // overflow fallback (practically never): exact scan of all codes
        for (int j = tid; j < KC; j += 256) {
            const float* e = emb + (size_t)j * DD;
            float d0 = 0.f, d1 = 0.f, d2 = 0.f, d3 = 0.f;
            #pragma unroll 4
            for (int d = 0; d < DD; d += 4) {
                d0 += zrow[d]     * e[d];
                d1 += zrow[d + 1] * e[d + 1];
                d2 += zrow[d + 2] * e[d + 2];
                d3 += zrow[d + 3] * e[d + 3];
            }
            float p = (d0 + d1) + (d2 + d3);
            float s = __fsub_rn(__fadd_rn(zn, g_enorm[j]), __fmul_rn(2.0f, p));
            if (s < bv || (s == bv && j < bi)) { bv = s; bi = j; }
        }
    }

    red[tid] = bv; redi[tid] = bi;
    __syncthreads();
    #pragma unroll
    for (int o = 128; o > 0; o >>= 1) {
        if (tid < o) {
            float ov = red[tid + o]; int oi = redi[tid + o];
            if (ov < red[tid] || (ov == red[tid] && oi < redi[tid])) {
                red[tid] = ov; redi[tid] = oi;
            }
        }
        __syncthreads();
    }
    if (tid == 0) {
        s_best = redi[0];
        g_idx[t] = redi[0];
        atomicAdd(&g_counts[redi[0]], 1.0f);
    }
    __syncthreads();
    atomicAdd(&g_dw[(size_t)s_best * DD + tid], zrow[tid]);
}

// ---------------- K3: new cluster size raw + global sum ----------------
__global__ void k_ncs(const float* __restrict__ cs) {
    __shared__ float sm[256];
    int k = blockIdx.x * 256 + threadIdx.x;
    float raw = cs[k] * 0.99f + 0.01f * g_counts[k];
    g_ncsraw[k] = raw;
    sm[threadIdx.x] = raw;
    __syncthreads();
    #pragma unroll
    for (int o = 128; o > 0; o >>= 1) {
        if (threadIdx.x < o) sm[threadIdx.x] += sm[threadIdx.x + o];
        __syncthreads();
    }
    if (threadIdx.x == 0) atomicAdd(&g_red[0], sm[0]);
}

// ---------------- K4: ema_w, embedding, new_cs outputs ----------------
__global__ void k_final(const float* __restrict__ emaw, float* __restrict__ out) {
    int i = blockIdx.x * 256 + threadIdx.x;
    int k = i >> 8, d = i & 255;
    float n = g_red[0];
    float ncs = (g_ncsraw[k] + 1e-5f) / (n + 0.08192f) * n;
    float w = emaw[i] * 0.99f + 0.01f * g_dw[i];
    out[OFF_EMAW + i] = w;
    out[OFF_EMB + i] = w / ncs;
    if (d == 0) out[OFF_CS + k] = ncs;
}

// ---------------- K5: z_q gather (NCHW) + loss partial sums ----------------
__global__ void k_zq(const float* __restrict__ z, const float* __restrict__ emb,
                     float* __restrict__ out) {
    __shared__ float sm[256];
    int i = blockIdx.x * 256 + threadIdx.x;   // over NELEM, memory-linear
    int b = i >> 18;
    int rem = i & 262143;
    int d = rem >> 10;
    int hw = rem & 1023;
    int n = (b << 10) | hw;
    float q = emb[(size_t)g_idx[n] * DD + d];
    out[OFF_ZQ + i] = q;
    float df = q - z[i];
    sm[threadIdx.x] = df * df;
    __syncthreads();
    #pragma unroll
    for (int o = 128; o > 0; o >>= 1) {
        if (threadIdx.x < o) sm[threadIdx.x] += sm[threadIdx.x + o];
        __syncthreads();
    }
    if (threadIdx.x == 0) atomicAdd(&g_red[1], sm[0]);
}

// ---------------- K6: loss scalar + idx (as float) ----------------
__global__ void k_tail(float* __restrict__ out) {
    int i = blockIdx.x * 256 + threadIdx.x;
    if (i < NT) out[OFF_IDX + i] = (float)g_idx[i];
    if (i == 0) out[OFF_LOSS] = 1.25f * g_red[1] / 2097152.0f;
}

// ---------------- launch ----------------
extern "C" void kernel_launch(void* const* d_in, const int* in_sizes, int n_in,
                              void* d_out, int out_size) {
    const float* z    = (const float*)d_in[0];
    const float* emb  = (const float*)d_in[1];
    const float* cs   = (const float*)d_in[2];
    const float* emaw = (const float*)d_in[3];
    float* out = (float*)d_out;

    cudaFuncSetAttribute(k_gemm, cudaFuncAttributeMaxDynamicSharedMemorySize, SMEM_GEMM);

    k_prep<<<KC, 256>>>(emb);
    k_transpose<<<dim3(32, 8, 8), dim3(32, 8)>>>(z);
    k_gemm<<<dim3(KC / BN, NT / BM), 256, SMEM_GEMM>>>();
    k_select<<<NT, 256>>>(emb);
    k_ncs<<<KC / 256, 256>>>(cs);
    k_final<<<KC * DD / 256, 256>>>(emaw, out);
    k_zq<<<NELEM / 256, 256>>>(z, emb, out);
    k_tail<<<32, 256>>>(out);
}

// round 6
// speedup vs baseline: 1.5196x; 1.0327x over previous
#include <cuda_runtime.h>
#include <cuda_bf16.h>
#include <cstdint>
#include <math_constants.h>

// Problem constants
#define NT 8192      // tokens = 8*32*32
#define KC 8192      // codebook size
#define DD 256       // embedding dim
#define BHW 1024     // 32*32
#define NELEM 2097152  // 8*256*32*32
#define CAP 64       // candidate list capacity per token

// Output layout (float32, concatenated in reference return order)
// NOTE: OFF_EMAW / OFF_EMB are == 1 (mod 4) -> NO vector stores there!
#define OFF_ZQ   0
#define OFF_LOSS 2097152
#define OFF_IDX  2097153
#define OFF_CS   2105345
#define OFF_EMAW 2113537
#define OFF_EMB  4210689

// ---------------- device scratch (no cudaMalloc allowed) ----------------
static __device__ __align__(16) __nv_bfloat16 g_zbf[(size_t)NT * DD];    // 4 MB
static __device__ __align__(16) __nv_bfloat16 g_ebf[(size_t)KC * DD];    // 4 MB
static __device__ __align__(16) float         g_zf[(size_t)NT * DD];     // 8 MB
static __device__ float         g_enorm[KC];
static __device__ unsigned      g_tokmax[NT];              // ordered-uint running max dot
static __device__ int           g_ccnt[NT];
static __device__ __align__(16) int2 g_cand[(size_t)NT * CAP];  // 4 MB
static __device__ __align__(16) int  g_idx[NT];
static __device__ float         g_counts[KC];
static __device__ __align__(16) float g_dw[(size_t)KC * DD];    // 8 MB
static __device__ float         g_ncsraw[KC];
static __device__ float         g_red[2];                  // [0]=sum(new_cs), [1]=loss sum

// ordered-uint encoding of float: monotonic for unsigned compare
__device__ __forceinline__ unsigned ford(float f) {
    unsigned b = __float_as_uint(f);
    return (b & 0x80000000u) ? ~b : (b | 0x80000000u);
}
__device__ __forceinline__ float iford(unsigned u) {
    unsigned b = (u & 0x80000000u) ? (u & 0x7fffffffu) : ~u;
    return __uint_as_float(b);
}

// ---------------- K0a: per-code prep: bf16 convert, ||e||^2, zero scratch ----
__global__ __launch_bounds__(256) void k_prep(const float* __restrict__ emb) {
    __shared__ float sm[256];
    int k = blockIdx.x, tid = threadIdx.x;
    float v = emb[(size_t)k * DD + tid];
    g_ebf[(size_t)k * DD + tid] = __float2bfloat16(v);
    g_dw[(size_t)k * DD + tid] = 0.0f;
    sm[tid] = v * v;
    __syncthreads();
    #pragma unroll
    for (int o = 128; o > 0; o >>= 1) {
        if (tid < o) sm[tid] += sm[tid + o];
        __syncthreads();
    }
    if (tid == 0) {
        g_enorm[k] = sm[0];
        g_counts[k] = 0.0f;
        g_tokmax[k] = 0u;     // below ford of any finite value
        g_ccnt[k] = 0;
        if (k < 2) g_red[k] = 0.0f;
    }
}

// ---------------- K0c: transpose z [B,C,H,W] -> [t][d] (bf16 + fp32) --------
__global__ void k_transpose(const float* __restrict__ z) {
    __shared__ float tile[32][33];
    int b = blockIdx.z, d0 = blockIdx.y * 32, hw0 = blockIdx.x * 32;
    int x = threadIdx.x, y = threadIdx.y;
    const float* zb = z + (size_t)b * (DD * BHW);
    #pragma unroll
    for (int yy = y; yy < 32; yy += 8)
        tile[yy][x] = zb[(size_t)(d0 + yy) * BHW + hw0 + x];
    __syncthreads();
    #pragma unroll
    for (int yy = y; yy < 32; yy += 8) {
        float v = tile[x][yy];
        size_t o = (size_t)(b * BHW + hw0 + yy) * DD + d0 + x;
        g_zbf[o] = __float2bfloat16(v);
        g_zf[o] = v;
    }
}

// ---------------- K1: bf16 GEMM (z.e) with fused argmax/candidate epilogue --
#define BM 128
#define BN 128
#define ASTRIDE 88   // 176B row stride: conflict-free, 16B aligned
#define BUFBYTES (2 * BM * ASTRIDE * 2)   // As+Bs per stage = 45056 B
#define SMEM_GEMM (2 * BUFBYTES)          // double buffered = 90112 B

__device__ __forceinline__ void mma16816(float* c, const unsigned* a, const unsigned* b) {
    asm volatile(
        "mma.sync.aligned.m16n8k16.row.col.f32.bf16.bf16.f32 "
        "{%0,%1,%2,%3}, {%4,%5,%6,%7}, {%8,%9}, {%0,%1,%2,%3};\n"
        : "+f"(c[0]), "+f"(c[1]), "+f"(c[2]), "+f"(c[3])
        : "r"(a[0]), "r"(a[1]), "r"(a[2]), "r"(a[3]), "r"(b[0]), "r"(b[1]));
}

__device__ __forceinline__ void cpasync16(void* smem, const void* g) {
    unsigned s = (unsigned)__cvta_generic_to_shared(smem);
    asm volatile("cp.async.cg.shared.global [%0], [%1], 16;\n" :: "r"(s), "l"(g));
}
#define CP_COMMIT() asm volatile("cp.async.commit_group;\n" ::: "memory")
#define CP_WAIT(n)  asm volatile("cp.async.wait_group %0;\n" :: "n"(n) : "memory")

__device__ __forceinline__ void load_tile(char* buf, int it, int t0, int k0, int tid) {
    __nv_bfloat16* As = (__nv_bfloat16*)buf;
    __nv_bfloat16* Bs = (__nv_bfloat16*)(buf + BM * ASTRIDE * 2);
    #pragma unroll
    for (int p = 0; p < 4; ++p) {
        int idx = p * 2048 + tid * 8;
        int row = idx >> 6, col = idx & 63;
        cpasync16(As + row * ASTRIDE + col,
                  g_zbf + (size_t)(t0 + row) * DD + it * 64 + col);
        cpasync16(Bs + row * ASTRIDE + col,
                  g_ebf + (size_t)(k0 + row) * DD + it * 64 + col);
    }
}

__global__ __launch_bounds__(256) void k_gemm() {
    extern __shared__ char dynbuf[];
    int t0 = blockIdx.y * BM, k0 = blockIdx.x * BN;
    int tid = threadIdx.x;
    int w = tid >> 5, lane = tid & 31;
    int wm = w >> 2, wn = w & 3;           // 2 x 4 warp grid, 64x32 warp tile
    int g = lane >> 2, tg = lane & 3;

    float acc[4][4][4];
    #pragma unroll
    for (int mi = 0; mi < 4; ++mi)
        #pragma unroll
        for (int ni = 0; ni < 4; ++ni)
            #pragma unroll
            for (int r = 0; r < 4; ++r) acc[mi][ni][r] = 0.0f;

    load_tile(dynbuf, 0, t0, k0, tid);
    CP_COMMIT();

    for (int it = 0; it < 4; ++it) {
        if (it < 3) {
            load_tile(dynbuf + ((it + 1) & 1) * BUFBYTES, it + 1, t0, k0, tid);
            CP_COMMIT();
            CP_WAIT(1);
        } else {
            CP_WAIT(0);
        }
        __syncthreads();

        char* buf = dynbuf + (it & 1) * BUFBYTES;
        __nv_bfloat16* As = (__nv_bfloat16*)buf;
        __nv_bfloat16* Bs = (__nv_bfloat16*)(buf + BM * ASTRIDE * 2);
        #pragma unroll
        for (int ks = 0; ks < 4; ++ks) {
            int kb = ks * 16;
            unsigned a[4][4], bfr[4][2];
            #pragma unroll
            for (int mi = 0; mi < 4; ++mi) {
                int r = (wm * 64 + mi * 16 + g) * ASTRIDE;
                a[mi][0] = *(unsigned*)(As + r + kb + tg * 2);
                a[mi][1] = *(unsigned*)(As + r + 8 * ASTRIDE + kb + tg * 2);
                a[mi][2] = *(unsigned*)(As + r + kb + 8 + tg * 2);
                a[mi][3] = *(unsigned*)(As + r + 8 * ASTRIDE + kb + 8 + tg * 2);
            }
            #pragma unroll
            for (int ni = 0; ni < 4; ++ni) {
                int r = (wn * 32 + ni * 8 + g) * ASTRIDE;
                bfr[ni][0] = *(unsigned*)(Bs + r + kb + tg * 2);
                bfr[ni][1] = *(unsigned*)(Bs + r + kb + 8 + tg * 2);
            }
            #pragma unroll
            for (int mi = 0; mi < 4; ++mi)
                #pragma unroll
                for (int ni = 0; ni < 4; ++ni)
                    mma16816(acc[mi][ni], a[mi], bfr[ni]);
        }
        __syncthreads();
    }

    // -------- fused epilogue: per-token running max + candidate append ------
    unsigned* srm = (unsigned*)dynbuf;          // [128] ordered-uint row max
    float*    sthr = (float*)(dynbuf + 512);    // [128] per-row threshold
    if (tid < 128) srm[tid] = 0u;
    __syncthreads();

    #pragma unroll
    for (int mi = 0; mi < 4; ++mi) {
        float m1 = -CUDART_INF_F, m2 = -CUDART_INF_F;
        #pragma unroll
        for (int ni = 0; ni < 4; ++ni) {
            m1 = fmaxf(m1, fmaxf(acc[mi][ni][0], acc[mi][ni][1]));
            m2 = fmaxf(m2, fmaxf(acc[mi][ni][2], acc[mi][ni][3]));
        }
        #pragma unroll
        for (int o = 1; o <= 2; o <<= 1) {
            m1 = fmaxf(m1, __shfl_xor_sync(0xffffffffu, m1, o));
            m2 = fmaxf(m2, __shfl_xor_sync(0xffffffffu, m2, o));
        }
        if (tg == 0) {
            int r1 = wm * 64 + mi * 16 + g;
            atomicMax(&srm[r1], ford(m1));
            atomicMax(&srm[r1 + 8], ford(m2));
        }
    }
    __syncthreads();

    if (tid < 128) {
        unsigned mine = srm[tid];
        unsigned old = atomicMax(&g_tokmax[t0 + tid], mine);
        unsigned cur = old > mine ? old : mine;
        sthr[tid] = iford(cur) - 4e-4f;
    }
    __syncthreads();

    #pragma unroll
    for (int mi = 0; mi < 4; ++mi) {
        int r1 = wm * 64 + mi * 16 + g;
        float th1 = sthr[r1], th2 = sthr[r1 + 8];
        #pragma unroll
        for (int ni = 0; ni < 4; ++ni) {
            int c0 = k0 + wn * 32 + ni * 8 + tg * 2;
            #pragma unroll
            for (int h = 0; h < 2; ++h) {
                float v1 = acc[mi][ni][h];
                if (v1 >= th1) {
                    int t = t0 + r1;
                    int pos = atomicAdd(&g_ccnt[t], 1);
                    if (pos < CAP) g_cand[(size_t)t * CAP + pos] =
                        make_int2(c0 + h, __float_as_int(v1));
                }
                float v2 = acc[mi][ni][2 + h];
                if (v2 >= th2) {
                    int t = t0 + r1 + 8;
                    int pos = atomicAdd(&g_ccnt[t], 1);
                    if (pos < CAP) g_cand[(size_t)t * CAP + pos] =
                        make_int2(c0 + h, __float_as_int(v2));
                }
            }
        }
    }
}

// ---------------- K2: warp-per-token exact fp32 rescore (reference rounding)
// Reference scores d = (||z||^2 + ||e||^2) - 2*(z.e) in fp32; ||z||^2 ~ 256
// buckets scores to ulp(||z||^2). Argmin is invariant to ulp-level shifts of
// our zn (same-binade grid shift). Candidate lists are supersets of all codes
// within 4e-4 of the max dot; extras can never win. Tie-break: lowest index.
__global__ __launch_bounds__(256) void k_select(const float* __restrict__ emb,
                                                float* __restrict__ out) {
    int t = blockIdx.x * 8 + (threadIdx.x >> 5);
    int lane = threadIdx.x & 31;

    const float* zp = g_zf + (size_t)t * DD + lane * 8;
    float4 za = *(const float4*)zp;
    float4 zb = *(const float4*)(zp + 4);
    float zr[8] = {za.x, za.y, za.z, za.w, zb.x, zb.y, zb.z, zb.w};

    float zn = 0.0f;
    #pragma unroll
    for (int q = 0; q < 8; ++q) zn += zr[q] * zr[q];
    #pragma unroll
    for (int o = 16; o > 0; o >>= 1) zn += __shfl_xor_sync(0xffffffffu, zn, o);

    int cnt = g_ccnt[t];
    float bv = CUDART_INF_F; int bi = 0x7fffffff;

    if (cnt <= CAP) {
        for (int c = 0; c < cnt; ++c) {
            int j = g_cand[(size_t)t * CAP + c].x;
            const float* e = emb + (size_t)j * DD + lane * 8;
            float4 ea = *(const float4*)e;
            float4 eb = *(const float4*)(e + 4);
            float p = zr[0] * ea.x + zr[1] * ea.y + zr[2] * ea.z + zr[3] * ea.w
                    + zr[4] * eb.x + zr[5] * eb.y + zr[6] * eb.z + zr[7] * eb.w;
            #pragma unroll
            for (int o = 16; o > 0; o >>= 1) p += __shfl_xor_sync(0xffffffffu, p, o);
            // all lanes hold identical p -> identical comparison, no divergence
            float s = __fsub_rn(__fadd_rn(zn, g_enorm[j]), __fmul_rn(2.0f, p));
            if (s < bv || (s == bv && j < bi)) { bv = s; bi = j; }
        }
    } else {
        // overflow fallback (practically unreachable): exact scan of all codes
        for (int j = lane; j < KC; j += 32) {
            const float* e = emb + (size_t)j * DD;
            float d0 = 0.f, d1 = 0.f, d2 = 0.f, d3 = 0.f;
            for (int d = 0; d < DD; d += 4) {
                d0 += g_zf[(size_t)t * DD + d]     * e[d];
                d1 += g_zf[(size_t)t * DD + d + 1] * e[d + 1];
                d2 += g_zf[(size_t)t * DD + d + 2] * e[d + 2];
                d3 += g_zf[(size_t)t * DD + d + 3] * e[d + 3];
            }
            float p = (d0 + d1) + (d2 + d3);
            float s = __fsub_rn(__fadd_rn(zn, g_enorm[j]), __fmul_rn(2.0f, p));
            if (s < bv || (s == bv && j < bi)) { bv = s; bi = j; }
        }
        #pragma unroll
        for (int o = 16; o > 0; o >>= 1) {
            float ov = __shfl_xor_sync(0xffffffffu, bv, o);
            int   oi = __shfl_xor_sync(0xffffffffu, bi, o);
            if (ov < bv || (ov == bv && oi < bi)) { bv = ov; bi = oi; }
        }
    }

    if (lane == 0) {
        g_idx[t] = bi;
        out[OFF_IDX + t] = (float)bi;
        atomicAdd(&g_counts[bi], 1.0f);
    }
    float* dwp = g_dw + (size_t)bi * DD + lane * 8;
    #pragma unroll
    for (int q = 0; q < 8; ++q) atomicAdd(dwp + q, zr[q]);
}

// ---------------- K3: new cluster size raw + global sum ----------------
__global__ void k_ncs(const float* __restrict__ cs) {
    __shared__ float sm[256];
    int k = blockIdx.x * 256 + threadIdx.x;
    float raw = cs[k] * 0.99f + 0.01f * g_counts[k];
    g_ncsraw[k] = raw;
    sm[threadIdx.x] = raw;
    __syncthreads();
    #pragma unroll
    for (int o = 128; o > 0; o >>= 1) {
        if (threadIdx.x < o) sm[threadIdx.x] += sm[threadIdx.x + o];
        __syncthreads();
    }
    if (threadIdx.x == 0) atomicAdd(&g_red[0], sm[0]);
}

// ---------------- K4: ema_w, embedding, new_cs outputs (scalar: the output
// offsets OFF_EMAW/OFF_EMB are odd multiples of 4 bytes -> no float4 stores) -
__global__ __launch_bounds__(256) void k_final(const float* __restrict__ emaw,
                                               float* __restrict__ out) {
    int i = blockIdx.x * 256 + threadIdx.x;
    int k = i >> 8, d = i & 255;
    float n = g_red[0];
    float ncs = (g_ncsraw[k] + 1e-5f) / (n + 0.08192f) * n;
    float w = emaw[i] * 0.99f + 0.01f * g_dw[i];
    out[OFF_EMAW + i] = w;
    out[OFF_EMB + i] = w / ncs;
    if (d == 0) out[OFF_CS + k] = ncs;
}

// ---------------- K5: z_q gather (NCHW, float4) + loss partial sums ---------
__global__ __launch_bounds__(256) void k_zq(const float* __restrict__ z,
                                            const float* __restrict__ emb,
                                            float* __restrict__ out) {
    int i4 = blockIdx.x * 256 + threadIdx.x;   // over NELEM/4
    int i = i4 * 4;
    int b = i >> 18;
    int rem = i & 262143;
    int d = rem >> 10;
    int hw = rem & 1023;                       // hw % 4 == 0
    int n = (b << 10) | hw;
    int4 idx4 = *(const int4*)(g_idx + n);     // 4 consecutive tokens, same d
    float4 q4;
    q4.x = emb[(size_t)idx4.x * DD + d];
    q4.y = emb[(size_t)idx4.y * DD + d];
    q4.z = emb[(size_t)idx4.z * DD + d];
    q4.w = emb[(size_t)idx4.w * DD + d];
    float4 z4 = ((const float4*)z)[i4];
    ((float4*)(out + OFF_ZQ))[i4] = q4;        // OFF_ZQ = 0: 16B aligned
    float dx = q4.x - z4.x, dy = q4.y - z4.y, dz = q4.z - z4.z, dw = q4.w - z4.w;
    float s = dx * dx + dy * dy + dz * dz + dw * dw;
    #pragma unroll
    for (int o = 16; o > 0; o >>= 1) s += __shfl_down_sync(0xffffffffu, s, o);
    if ((threadIdx.x & 31) == 0) atomicAdd(&g_red[1], s);
}

// ---------------- K6: loss scalar ----------------
__global__ void k_tail(float* __restrict__ out) {
    out[OFF_LOSS] = 1.25f * g_red[1] / 2097152.0f;
}

// ---------------- launch ----------------
extern "C" void kernel_launch(void* const* d_in, const int* in_sizes, int n_in,
                              void* d_out, int out_size) {
    const float* z    = (const float*)d_in[0];
    const float* emb  = (const float*)d_in[1];
    const float* cs   = (const float*)d_in[2];
    const float* emaw = (const float*)d_in[3];
    float* out = (float*)d_out;

    cudaFuncSetAttribute(k_gemm, cudaFuncAttributeMaxDynamicSharedMemorySize, SMEM_GEMM);

    k_prep<<<KC, 256>>>(emb);
    k_transpose<<<dim3(32, 8, 8), dim3(32, 8)>>>(z);
    k_gemm<<<dim3(KC / BN, NT / BM), 256, SMEM_GEMM>>>();
    k_select<<<NT / 8, 256>>>(emb, out);
    k_ncs<<<KC / 256, 256>>>(cs);
    k_final<<<KC * DD / 256, 256>>>(emaw, out);
    k_zq<<<NELEM / 1024, 256>>>(z, emb, out);
    k_tail<<<1, 1>>>(out);
}

// round 8
// speedup vs baseline: 1.6921x; 1.1136x over previous
#include <cuda_runtime.h>
#include <cuda_bf16.h>
#include <cstdint>
#include <math_constants.h>

// Problem constants
#define NT 8192      // tokens = 8*32*32
#define KC 8192      // codebook size
#define DD 256       // embedding dim
#define BHW 1024     // 32*32
#define NELEM 2097152  // 8*256*32*32
#define CAP 64       // candidate list capacity per token
#define MARGIN 2.5e-4f  // bf16-input dot err (worst ~2e-5) + fp32 bucket (3e-5), 5x headroom

// Output layout (float32, concatenated in reference return order)
// NOTE: OFF_EMAW / OFF_EMB are == 1 (mod 4) -> NO vector stores there!
#define OFF_ZQ   0
#define OFF_LOSS 2097152
#define OFF_IDX  2097153
#define OFF_CS   2105345
#define OFF_EMAW 2113537
#define OFF_EMB  4210689

// ---------------- device scratch (no cudaMalloc allowed) ----------------
static __device__ __align__(16) __nv_bfloat16 g_zbf[(size_t)NT * DD];    // 4 MB
static __device__ __align__(16) __nv_bfloat16 g_ebf[(size_t)KC * DD];    // 4 MB
static __device__ __align__(16) float         g_zf[(size_t)NT * DD];     // 8 MB
static __device__ float         g_enorm[KC];
static __device__ unsigned      g_tokmax[NT];              // ordered-uint running max dot
static __device__ int           g_ccnt[NT];
static __device__ __align__(16) int2 g_cand[(size_t)NT * CAP];  // 4 MB
static __device__ __align__(16) int  g_idx[NT];
static __device__ float         g_counts[KC];
static __device__ __align__(16) float g_dw[(size_t)KC * DD];    // 8 MB
static __device__ float         g_ncsraw[KC];
static __device__ float         g_red[2];                  // [0]=sum(new_cs), [1]=loss sum

// ordered-uint encoding of float: monotonic for unsigned compare
__device__ __forceinline__ unsigned ford(float f) {
    unsigned b = __float_as_uint(f);
    return (b & 0x80000000u) ? ~b : (b | 0x80000000u);
}
__device__ __forceinline__ float iford(unsigned u) {
    unsigned b = (u & 0x80000000u) ? (u & 0x7fffffffu) : ~u;
    return __uint_as_float(b);
}

// ---------------- K0a: per-code prep: bf16 convert, ||e||^2, zero scratch ----
__global__ __launch_bounds__(256) void k_prep(const float* __restrict__ emb) {
    __shared__ float sm[256];
    int k = blockIdx.x, tid = threadIdx.x;
    float v = emb[(size_t)k * DD + tid];
    g_ebf[(size_t)k * DD + tid] = __float2bfloat16(v);
    g_dw[(size_t)k * DD + tid] = 0.0f;
    sm[tid] = v * v;
    __syncthreads();
    #pragma unroll
    for (int o = 128; o > 0; o >>= 1) {
        if (tid < o) sm[tid] += sm[tid + o];
        __syncthreads();
    }
    if (tid == 0) {
        g_enorm[k] = sm[0];
        g_counts[k] = 0.0f;
        g_tokmax[k] = 0u;     // below ford of any finite value
        g_ccnt[k] = 0;
        if (k < 2) g_red[k] = 0.0f;
    }
}

// ---------------- K0c: transpose z [B,C,H,W] -> [t][d] (bf16 + fp32) --------
__global__ void k_transpose(const float* __restrict__ z) {
    __shared__ float tile[32][33];
    int b = blockIdx.z, d0 = blockIdx.y * 32, hw0 = blockIdx.x * 32;
    int x = threadIdx.x, y = threadIdx.y;
    const float* zb = z + (size_t)b * (DD * BHW);
    #pragma unroll
    for (int yy = y; yy < 32; yy += 8)
        tile[yy][x] = zb[(size_t)(d0 + yy) * BHW + hw0 + x];
    __syncthreads();
    #pragma unroll
    for (int yy = y; yy < 32; yy += 8) {
        float v = tile[x][yy];
        size_t o = (size_t)(b * BHW + hw0 + yy) * DD + d0 + x;
        g_zbf[o] = __float2bfloat16(v);
        g_zf[o] = v;
    }
}

// ---------------- K1: bf16 GEMM (z.e) with fused argmax/candidate epilogue --
#define BM 128
#define BN 128
#define ASTRIDE 88   // 176B row stride: conflict-free for ldmatrix, 16B aligned
#define BUFBYTES (2 * BM * ASTRIDE * 2)   // As+Bs per stage = 45056 B
#define SMEM_GEMM (2 * BUFBYTES)          // double buffered = 90112 B

__device__ __forceinline__ void mma16816(float* c, const unsigned* a, const unsigned* b) {
    asm volatile(
        "mma.sync.aligned.m16n8k16.row.col.f32.bf16.bf16.f32 "
        "{%0,%1,%2,%3}, {%4,%5,%6,%7}, {%8,%9}, {%0,%1,%2,%3};\n"
        : "+f"(c[0]), "+f"(c[1]), "+f"(c[2]), "+f"(c[3])
        : "r"(a[0]), "r"(a[1]), "r"(a[2]), "r"(a[3]), "r"(b[0]), "r"(b[1]));
}

__device__ __forceinline__ void ldsm_x4(unsigned* r, uint32_t addr) {
    asm volatile("ldmatrix.sync.aligned.m8n8.x4.shared.b16 {%0,%1,%2,%3}, [%4];"
        : "=r"(r[0]), "=r"(r[1]), "=r"(r[2]), "=r"(r[3]) : "r"(addr));
}
__device__ __forceinline__ void ldsm_x2(unsigned* r, uint32_t addr) {
    asm volatile("ldmatrix.sync.aligned.m8n8.x2.shared.b16 {%0,%1}, [%2];"
        : "=r"(r[0]), "=r"(r[1]) : "r"(addr));
}

__device__ __forceinline__ void cpasync16(void* smem, const void* g) {
    unsigned s = (unsigned)__cvta_generic_to_shared(smem);
    asm volatile("cp.async.cg.shared.global [%0], [%1], 16;\n" :: "r"(s), "l"(g));
}
#define CP_COMMIT() asm volatile("cp.async.commit_group;\n" ::: "memory")
#define CP_WAIT(n)  asm volatile("cp.async.wait_group %0;\n" :: "n"(n) : "memory")

__device__ __forceinline__ void load_tile(char* buf, int it, int t0, int k0, int tid) {
    __nv_bfloat16* As = (__nv_bfloat16*)buf;
    __nv_bfloat16* Bs = (__nv_bfloat16*)(buf + BM * ASTRIDE * 2);
    #pragma unroll
    for (int p = 0; p < 4; ++p) {
        int idx = p * 2048 + tid * 8;
        int row = idx >> 6, col = idx & 63;
        cpasync16(As + row * ASTRIDE + col,
                  g_zbf + (size_t)(t0 + row) * DD + it * 64 + col);
        cpasync16(Bs + row * ASTRIDE + col,
                  g_ebf + (size_t)(k0 + row) * DD + it * 64 + col);
    }
}

__global__ __launch_bounds__(256) void k_gemm() {
    extern __shared__ char dynbuf[];
    uint32_t sbase = (uint32_t)__cvta_generic_to_shared(dynbuf);
    int t0 = blockIdx.y * BM, k0 = blockIdx.x * BN;
    int tid = threadIdx.x;
    int w = tid >> 5, lane = tid & 31;
    int wm = w >> 2, wn = w & 3;           // 2 x 4 warp grid, 64x32 warp tile
    int g = lane >> 2, tg = lane & 3;
    int lr = lane & 7, quad = lane >> 3;

    // ldmatrix per-lane byte offsets (within a stage buffer)
    // A x4: quad0 -> rows+0 k0 | quad1 -> rows+8 k0 | quad2 -> rows+0 k8 | quad3 -> rows+8 k8
    uint32_t a_off = ((wm * 64 + lr + (quad & 1) * 8) * ASTRIDE + (quad >> 1) * 8) * 2;
    // B x2: lanes 0-7 -> col kb, lanes 8-15 -> col kb+8 (lanes 16-31 ignored)
    uint32_t b_off = (uint32_t)(BM * ASTRIDE * 2) + ((wn * 32 + lr) * ASTRIDE) * 2
                   + ((quad & 1) ? 16u : 0u);

    float acc[4][4][4];
    #pragma unroll
    for (int mi = 0; mi < 4; ++mi)
        #pragma unroll
        for (int ni = 0; ni < 4; ++ni)
            #pragma unroll
            for (int r = 0; r < 4; ++r) acc[mi][ni][r] = 0.0f;

    load_tile(dynbuf, 0, t0, k0, tid);
    CP_COMMIT();

    for (int it = 0; it < 4; ++it) {
        if (it < 3) {
            load_tile(dynbuf + ((it + 1) & 1) * BUFBYTES, it + 1, t0, k0, tid);
            CP_COMMIT();
            CP_WAIT(1);
        } else {
            CP_WAIT(0);
        }
        __syncthreads();

        uint32_t bufb = sbase + (it & 1) * BUFBYTES;
        #pragma unroll
        for (int ks = 0; ks < 4; ++ks) {
            uint32_t kb2 = ks * 32;        // ks*16 elements * 2 bytes
            unsigned a[4][4], bfr[4][2];
            #pragma unroll
            for (int mi = 0; mi < 4; ++mi)
                ldsm_x4(a[mi], bufb + a_off + mi * (16 * ASTRIDE * 2) + kb2);
            #pragma unroll
            for (int ni = 0; ni < 4; ++ni)
                ldsm_x2(bfr[ni], bufb + b_off + ni * (8 * ASTRIDE * 2) + kb2);
            #pragma unroll
            for (int mi = 0; mi < 4; ++mi)
                #pragma unroll
                for (int ni = 0; ni < 4; ++ni)
                    mma16816(acc[mi][ni], a[mi], bfr[ni]);
        }
        __syncthreads();
    }

    // -------- fused epilogue: per-token running max + candidate append ------
    unsigned* srm = (unsigned*)dynbuf;          // [128] ordered-uint row max
    float*    sthr = (float*)(dynbuf + 512);    // [128] per-row threshold
    if (tid < 128) srm[tid] = 0u;
    __syncthreads();

    #pragma unroll
    for (int mi = 0; mi < 4; ++mi) {
        float m1 = -CUDART_INF_F, m2 = -CUDART_INF_F;
        #pragma unroll
        for (int ni = 0; ni < 4; ++ni) {
            m1 = fmaxf(m1, fmaxf(acc[mi][ni][0], acc[mi][ni][1]));
            m2 = fmaxf(m2, fmaxf(acc[mi][ni][2], acc[mi][ni][3]));
        }
        #pragma unroll
        for (int o = 1; o <= 2; o <<= 1) {
            m1 = fmaxf(m1, __shfl_xor_sync(0xffffffffu, m1, o));
            m2 = fmaxf(m2, __shfl_xor_sync(0xffffffffu, m2, o));
        }
        if (tg == 0) {
            int r1 = wm * 64 + mi * 16 + g;
            atomicMax(&srm[r1], ford(m1));
            atomicMax(&srm[r1 + 8], ford(m2));
        }
    }
    __syncthreads();

    if (tid < 128) {
        unsigned mine = srm[tid];
        unsigned old = atomicMax(&g_tokmax[t0 + tid], mine);
        unsigned cur = old > mine ? old : mine;
        sthr[tid] = iford(cur) - MARGIN;
    }
    __syncthreads();

    #pragma unroll
    for (int mi = 0; mi < 4; ++mi) {
        int r1 = wm * 64 + mi * 16 + g;
        float th1 = sthr[r1], th2 = sthr[r1 + 8];
        #pragma unroll
        for (int ni = 0; ni < 4; ++ni) {
            int c0 = k0 + wn * 32 + ni * 8 + tg * 2;
            #pragma unroll
            for (int h = 0; h < 2; ++h) {
                float v1 = acc[mi][ni][h];
                if (v1 >= th1) {
                    int t = t0 + r1;
                    int pos = atomicAdd(&g_ccnt[t], 1);
                    if (pos < CAP) g_cand[(size_t)t * CAP + pos] =
                        make_int2(c0 + h, __float_as_int(v1));
                }
                float v2 = acc[mi][ni][2 + h];
                if (v2 >= th2) {
                    int t = t0 + r1 + 8;
                    int pos = atomicAdd(&g_ccnt[t], 1);
                    if (pos < CAP) g_cand[(size_t)t * CAP + pos] =
                        make_int2(c0 + h, __float_as_int(v2));
                }
            }
        }
    }
}

// ---------------- K2: warp-per-token exact fp32 rescore (reference rounding)
// Reference scores d = (||z||^2 + ||e||^2) - 2*(z.e) in fp32; ||z||^2 ~ 256
// buckets scores to ulp(||z||^2). Argmin invariant to ulp-level shifts of our
// zn. Candidate lists are supersets of all possible reference winners (stale
// running-max thresholds only ADD candidates). Pre-prune against the list max
// (fp32-accumulated MMA dots) drops those extras before any embedding-row
// load; survivors get the literal-fp32 rescore. Tie-break: lowest index.
__global__ __launch_bounds__(256) void k_select(const float* __restrict__ emb,
                                                float* __restrict__ out) {
    int t = blockIdx.x * 8 + (threadIdx.x >> 5);
    int lane = threadIdx.x & 31;

    const float* zp = g_zf + (size_t)t * DD + lane * 8;
    float4 za = *(const float4*)zp;
    float4 zb = *(const float4*)(zp + 4);
    float zr[8] = {za.x, za.y, za.z, za.w, zb.x, zb.y, zb.z, zb.w};

    float zn = 0.0f;
    #pragma unroll
    for (int q = 0; q < 8; ++q) zn += zr[q] * zr[q];
    #pragma unroll
    for (int o = 16; o > 0; o >>= 1) zn += __shfl_xor_sync(0xffffffffu, zn, o);

    int cnt = g_ccnt[t];
    float bv = CUDART_INF_F; int bi = 0x7fffffff;

    if (cnt <= CAP) {
        // pre-prune: max of stored fp32 dots, keep only within MARGIN
        float pmax = -CUDART_INF_F;
        for (int c = lane; c < cnt; c += 32)
            pmax = fmaxf(pmax, __int_as_float(g_cand[(size_t)t * CAP + c].y));
        #pragma unroll
        for (int o = 16; o > 0; o >>= 1)
            pmax = fmaxf(pmax, __shfl_xor_sync(0xffffffffu, pmax, o));
        float pthr = pmax - MARGIN;

        for (int c = 0; c < cnt; ++c) {
            int2 cd = g_cand[(size_t)t * CAP + c];
            if (__int_as_float(cd.y) < pthr) continue;
            int j = cd.x;
            const float* e = emb + (size_t)j * DD + lane * 8;
            float4 ea = *(const float4*)e;
            float4 eb = *(const float4*)(e + 4);
            float p = zr[0] * ea.x + zr[1] * ea.y + zr[2] * ea.z + zr[3] * ea.w
                    + zr[4] * eb.x + zr[5] * eb.y + zr[6] * eb.z + zr[7] * eb.w;
            #pragma unroll
            for (int o = 16; o > 0; o >>= 1) p += __shfl_xor_sync(0xffffffffu, p, o);
            // all lanes hold identical p -> identical comparison, no divergence
            float s = __fsub_rn(__fadd_rn(zn, g_enorm[j]), __fmul_rn(2.0f, p));
            if (s < bv || (s == bv && j < bi)) { bv = s; bi = j; }
        }
    } else {
        // overflow fallback (practically unreachable): exact scan of all codes
        for (int j = lane; j < KC; j += 32) {
            const float* e = emb + (size_t)j * DD;
            float d0 = 0.f, d1 = 0.f, d2 = 0.f, d3 = 0.f;
            for (int d = 0; d < DD; d += 4) {
                d0 += g_zf[(size_t)t * DD + d]     * e[d];
                d1 += g_zf[(size_t)t * DD + d + 1] * e[d + 1];
                d2 += g_zf[(size_t)t * DD + d + 2] * e[d + 2];
                d3 += g_zf[(size_t)t * DD + d + 3] * e[d + 3];
            }
            float p = (d0 + d1) + (d2 + d3);
            float s = __fsub_rn(__fadd_rn(zn, g_enorm[j]), __fmul_rn(2.0f, p));
            if (s < bv || (s == bv && j < bi)) { bv = s; bi = j; }
        }
        #pragma unroll
        for (int o = 16; o > 0; o >>= 1) {
            float ov = __shfl_xor_sync(0xffffffffu, bv, o);
            int   oi = __shfl_xor_sync(0xffffffffu, bi, o);
            if (ov < bv || (ov == bv && oi < bi)) { bv = ov; bi = oi; }
        }
    }

    if (lane == 0) {
        g_idx[t] = bi;
        out[OFF_IDX + t] = (float)bi;
        atomicAdd(&g_counts[bi], 1.0f);
    }
    float* dwp = g_dw + (size_t)bi * DD + lane * 8;
    #pragma unroll
    for (int q = 0; q < 8; ++q) atomicAdd(dwp + q, zr[q]);
}

// ---------------- K3: new cluster size raw + global sum ----------------
__global__ void k_ncs(const float* __restrict__ cs) {
    __shared__ float sm[256];
    int k = blockIdx.x * 256 + threadIdx.x;
    float raw = cs[k] * 0.99f + 0.01f * g_counts[k];
    g_ncsraw[k] = raw;
    sm[threadIdx.x] = raw;
    __syncthreads();
    #pragma unroll
    for (int o = 128; o > 0; o >>= 1) {
        if (threadIdx.x < o) sm[threadIdx.x] += sm[threadIdx.x + o];
        __syncthreads();
    }
    if (threadIdx.x == 0) atomicAdd(&g_red[0], sm[0]);
}

// ---------------- K4: ema_w, embedding, new_cs outputs (scalar: the output
// offsets OFF_EMAW/OFF_EMB are odd multiples of 4 bytes -> no float4 stores) -
__global__ __launch_bounds__(256) void k_final(const float* __restrict__ emaw,
                                               float* __restrict__ out) {
    int i = blockIdx.x * 256 + threadIdx.x;
    int k = i >> 8, d = i & 255;
    float n = g_red[0];
    float ncs = (g_ncsraw[k] + 1e-5f) / (n + 0.08192f) * n;
    float w = emaw[i] * 0.99f + 0.01f * g_dw[i];
    out[OFF_EMAW + i] = w;
    out[OFF_EMB + i] = w / ncs;
    if (d == 0) out[OFF_CS + k] = ncs;
}

// ---------------- K5: z_q gather (NCHW, float4) + loss partial sums ---------
__global__ __launch_bounds__(256) void k_zq(const float* __restrict__ z,
                                            const float* __restrict__ emb,
                                            float* __restrict__ out) {
    int i4 = blockIdx.x * 256 + threadIdx.x;   // over NELEM/4
    int i = i4 * 4;
    int b = i >> 18;
    int rem = i & 262143;
    int d = rem >> 10;
    int hw = rem & 1023;                       // hw % 4 == 0
    int n = (b << 10) | hw;
    int4 idx4 = *(const int4*)(g_idx + n);     // 4 consecutive tokens, same d
    float4 q4;
    q4.x = emb[(size_t)idx4.x * DD + d];
    q4.y = emb[(size_t)idx4.y * DD + d];
    q4.z = emb[(size_t)idx4.z * DD + d];
    q4.w = emb[(size_t)idx4.w * DD + d];
    float4 z4 = ((const float4*)z)[i4];
    ((float4*)(out + OFF_ZQ))[i4] = q4;        // OFF_ZQ = 0: 16B aligned
    float dx = q4.x - z4.x, dy = q4.y - z4.y, dz = q4.z - z4.z, dw = q4.w - z4.w;
    float s = dx * dx + dy * dy + dz * dz + dw * dw;
    #pragma unroll
    for (int o = 16; o > 0; o >>= 1) s += __shfl_down_sync(0xffffffffu, s, o);
    if ((threadIdx.x & 31) == 0) atomicAdd(&g_red[1], s);
}

// ---------------- K6: loss scalar ----------------
__global__ void k_tail(float* __restrict__ out) {
    out[OFF_LOSS] = 1.25f * g_red[1] / 2097152.0f;
}

// ---------------- launch ----------------
extern "C" void kernel_launch(void* const* d_in, const int* in_sizes, int n_in,
                              void* d_out, int out_size) {
    const float* z    = (const float*)d_in[0];
    const float* emb  = (const float*)d_in[1];
    const float* cs   = (const float*)d_in[2];
    const float* emaw = (const float*)d_in[3];
    float* out = (float*)d_out;

    cudaFuncSetAttribute(k_gemm, cudaFuncAttributeMaxDynamicSharedMemorySize, SMEM_GEMM);

    k_prep<<<KC, 256>>>(emb);
    k_transpose<<<dim3(32, 8, 8), dim3(32, 8)>>>(z);
    k_gemm<<<dim3(KC / BN, NT / BM), 256, SMEM_GEMM>>>();
    k_select<<<NT / 8, 256>>>(emb, out);
    k_ncs<<<KC / 256, 256>>>(cs);
    k_final<<<KC * DD / 256, 256>>>(emaw, out);
    k_zq<<<NELEM / 1024, 256>>>(z, emb, out);
    k_tail<<<1, 1>>>(out);
}